// round 17
// baseline (speedup 1.0000x reference)
#include <cuda_runtime.h>
#include <cuda_fp16.h>
#include <math.h>
#include <stdint.h>

#define BB 4
#define TT 2048
#define CC 1024
#define HH 16
#define DD 64
#define MM (BB*TT)

// ---------------- scratch (device globals; no runtime alloc) ----------------
__device__ __half g_qh[(size_t)BB*HH*TT*DD], g_ql[(size_t)BB*HH*TT*DD];
__device__ __half g_kh[(size_t)BB*HH*TT*DD], g_kl[(size_t)BB*HH*TT*DD];
__device__ __half g_vh[(size_t)BB*HH*TT*DD], g_vl[(size_t)BB*HH*TT*DD];
__device__ __half g_xh[(size_t)MM*CC], g_xl[(size_t)MM*CC];
__device__ __half g_ah[(size_t)MM*CC], g_al[(size_t)MM*CC];
__device__ __half g_wh[4][(size_t)CC*CC];

// ---------------- base-ISA tensor helpers (compute_103-safe) ----------------
__device__ __forceinline__ uint32_t smem_u32(const void* p) {
    uint32_t a;
    asm("{ .reg .u64 t; cvta.to.shared.u64 t, %1; cvt.u32.u64 %0, t; }"
        : "=r"(a) : "l"(p));
    return a;
}
__device__ __forceinline__ void cp16(uint32_t dst, const void* src) {
    asm volatile("cp.async.cg.shared.global [%0], [%1], 16;" :: "r"(dst), "l"(src));
}
__device__ __forceinline__ void cp_commit() { asm volatile("cp.async.commit_group;"); }
template<int N> __device__ __forceinline__ void cp_wait() {
    asm volatile("cp.async.wait_group %0;" :: "n"(N));
}
__device__ __forceinline__ void ldsm4(uint32_t* r, uint32_t addr) {
    asm volatile("ldmatrix.sync.aligned.m8n8.x4.shared.b16 {%0,%1,%2,%3}, [%4];"
                 : "=r"(r[0]), "=r"(r[1]), "=r"(r[2]), "=r"(r[3]) : "r"(addr));
}
__device__ __forceinline__ void ldsm4t(uint32_t* r, uint32_t addr) {
    asm volatile("ldmatrix.sync.aligned.m8n8.x4.trans.shared.b16 {%0,%1,%2,%3}, [%4];"
                 : "=r"(r[0]), "=r"(r[1]), "=r"(r[2]), "=r"(r[3]) : "r"(addr));
}
// f32-accumulator HMMA (main passes)
__device__ __forceinline__ void mma16816(float* d, const uint32_t* a, const uint32_t* b) {
    asm volatile(
        "mma.sync.aligned.m16n8k16.row.col.f32.f16.f16.f32 "
        "{%0,%1,%2,%3}, {%4,%5,%6,%7}, {%8,%9}, {%0,%1,%2,%3};"
        : "+f"(d[0]), "+f"(d[1]), "+f"(d[2]), "+f"(d[3])
        : "r"(a[0]), "r"(a[1]), "r"(a[2]), "r"(a[3]), "r"(b[0]), "r"(b[1]));
}
// f16-accumulator HMMA (correction passes — values ~2^-12, precision ample)
__device__ __forceinline__ void mma16816h(uint32_t& d0, uint32_t& d1,
                                          const uint32_t* a, const uint32_t* b) {
    asm volatile(
        "mma.sync.aligned.m16n8k16.row.col.f16.f16.f16.f16 "
        "{%0,%1}, {%2,%3,%4,%5}, {%6,%7}, {%0,%1};"
        : "+r"(d0), "+r"(d1)
        : "r"(a[0]), "r"(a[1]), "r"(a[2]), "r"(a[3]), "r"(b[0]), "r"(b[1]));
}
// fold f16x2 correction fragment into f32 accumulator fragment
__device__ __forceinline__ void fold_h2(float* acc, uint32_t d0, uint32_t d1) {
    float2 f0 = __half22float2(*reinterpret_cast<__half2*>(&d0));
    float2 f1 = __half22float2(*reinterpret_cast<__half2*>(&d1));
    acc[0] += f0.x; acc[1] += f0.y; acc[2] += f1.x; acc[3] += f1.y;
}
__device__ __forceinline__ void splitpack(float a, float b, uint32_t& h, uint32_t& l) {
    __half2 hh = __floats2half2_rn(a, b);
    float2 hf = __half22float2(hh);
    __half2 ll = __floats2half2_rn(a - hf.x, b - hf.y);
    h = *reinterpret_cast<uint32_t*>(&hh);
    l = *reinterpret_cast<uint32_t*>(&ll);
}
__device__ __forceinline__ uint32_t pack_h2(float a, float b) {
    __half2 hh = __floats2half2_rn(a, b);
    return *reinterpret_cast<uint32_t*>(&hh);
}

// ---------------------------------------------------------------------------
// fp32 -> (fp16 hi, fp16 lo) split kernels
// ---------------------------------------------------------------------------
__global__ __launch_bounds__(256) void split_half(const float* __restrict__ src,
                                                  __half* __restrict__ hi,
                                                  __half* __restrict__ lo, int n4) {
    int i = blockIdx.x * 256 + threadIdx.x;
    if (i >= n4) return;
    float4 v = ((const float4*)src)[i];
    uint32_t h0, l0, h1, l1;
    splitpack(v.x, v.y, h0, l0);
    splitpack(v.z, v.w, h1, l1);
    ((uint32_t*)hi)[2 * i] = h0; ((uint32_t*)hi)[2 * i + 1] = h1;
    ((uint32_t*)lo)[2 * i] = l0; ((uint32_t*)lo)[2 * i + 1] = l1;
}
__global__ __launch_bounds__(256) void split_w4(const float* __restrict__ w0,
                                                const float* __restrict__ w1,
                                                const float* __restrict__ w2,
                                                const float* __restrict__ w3,
                                                __half* __restrict__ hi) {
    const int which = blockIdx.y;
    const float* src = which == 0 ? w0 : which == 1 ? w1 : which == 2 ? w2 : w3;
    hi += (size_t)which * CC * CC;
    int i = blockIdx.x * 256 + threadIdx.x;
    if (i >= CC * CC / 4) return;
    float4 v = ((const float4*)src)[i];
    ((uint32_t*)hi)[2 * i]     = pack_h2(v.x, v.y);
    ((uint32_t*)hi)[2 * i + 1] = pack_h2(v.z, v.w);
}

// ---------------------------------------------------------------------------
// GEMM core: D = (Ah + Al) * Bh. Main pass f32-acc; Al*Bh correction f16-acc
// folded per (mt,nt) step. Stage = Ah | Al | Bh, K-chunk 32, double-buffered.
// ---------------------------------------------------------------------------
#define ROWB 80
#define MATB (128 * ROWB)
#define STAGEB (3 * MATB)          // 30720
#define NCHUNK (CC / 32)

template<int REMAP>
__device__ __forceinline__ void gemm_core(
    const __half* __restrict__ Ah_g, const __half* __restrict__ Al_g,
    const __half* __restrict__ Bh_g,
    float* __restrict__ outF, __half* __restrict__ outH,
    __half* __restrict__ outL, char* smem, int m0, int n0) {

    const int tid = threadIdx.x;
    const int wid = tid >> 5;
    const int lane = tid & 31;
    const uint32_t sbase = smem_u32(smem);

    const char* srcs[3] = {
        (const char*)(Ah_g + (size_t)m0 * CC), (const char*)(Al_g + (size_t)m0 * CC),
        (const char*)(Bh_g + (size_t)n0 * CC)};

    auto stage_load = [&](int kc, int st) {
        const uint32_t dst0 = sbase + st * STAGEB;
        const size_t koff = (size_t)kc * 64;
#pragma unroll
        for (int mtx = 0; mtx < 3; mtx++) {
#pragma unroll
            for (int h2 = 0; h2 < 2; h2++) {
                const int idx = h2 * 256 + tid;
                const int r = idx >> 2, c = idx & 3;
                cp16(dst0 + mtx * MATB + r * ROWB + c * 16,
                     srcs[mtx] + (size_t)r * 2048 + koff + c * 16);
            }
        }
    };

    const int wm = wid >> 2, wn = wid & 3;
    const int g = lane >> 2, tig = lane & 3;
    float acc[4][4][4] = {};

    const int a_row = wm * 64 + (lane & 15);
    const int a_col = (lane >> 4) * 16;
    const int b_row = wn * 32 + (lane & 7) + ((lane >> 4) & 1) * 8;
    const int b_col = ((lane >> 3) & 1) * 16;

    stage_load(0, 0);
    cp_commit();

    for (int c = 0; c < NCHUNK; c++) {
        const int st = c & 1;
        if (c + 1 < NCHUNK) { stage_load(c + 1, (c + 1) & 1); cp_commit(); cp_wait<1>(); }
        else                { cp_wait<0>(); }
        __syncthreads();

        const uint32_t sAh = sbase + st * STAGEB;
        const uint32_t sAl = sAh + MATB;
        const uint32_t sBh = sAh + 2 * MATB;

#pragma unroll
        for (int s = 0; s < 2; s++) {
            const int k16 = s * 32;
            uint32_t bfh[2][4];
#pragma unroll
            for (int np = 0; np < 2; np++)
                ldsm4(bfh[np], sBh + (b_row + np * 16) * ROWB + b_col + k16);
#pragma unroll
            for (int mt = 0; mt < 4; mt++) {
                uint32_t afh[4], afl[4];
                const uint32_t ao = (a_row + mt * 16) * ROWB + a_col + k16;
                ldsm4(afh, sAh + ao);
                ldsm4(afl, sAl + ao);
#pragma unroll
                for (int nt = 0; nt < 4; nt++) {
                    const int np = nt >> 1, hf = (nt & 1) * 2;
                    mma16816(acc[mt][nt], afh, &bfh[np][hf]);
                    uint32_t c0 = 0, c1 = 0;
                    mma16816h(c0, c1, afl, &bfh[np][hf]);
                    fold_h2(acc[mt][nt], c0, c1);
                }
            }
        }
        __syncthreads();
    }

#pragma unroll
    for (int mt = 0; mt < 4; mt++) {
#pragma unroll
        for (int half = 0; half < 2; half++) {
            const int m = m0 + wm * 64 + mt * 16 + g + half * 8;
#pragma unroll
            for (int nt = 0; nt < 4; nt++) {
                const int n = n0 + wn * 32 + nt * 8 + tig * 2;
                const float v0 = acc[mt][nt][half * 2], v1 = acc[mt][nt][half * 2 + 1];
                if (REMAP) {
                    const int b = m >> 11, t = m & 2047;
                    const int h2 = (n & 1023) >> 6, d = n & 63;
                    const size_t off = (((size_t)(b * HH + h2)) * TT + t) * DD + d;
                    uint32_t ph, pl;
                    splitpack(v0, v1, ph, pl);
                    *(uint32_t*)(outH + off) = ph;
                    *(uint32_t*)(outL + off) = pl;
                } else {
                    *(float2*)(outF + (size_t)m * CC + n) = make_float2(v0, v1);
                }
            }
        }
    }
}

// Fused QKV: grid (24, 64). bid.x: [0,8)=Q, [8,16)=K, [16,24)=V.
__global__ __launch_bounds__(256) void qkv_gemm() {
    extern __shared__ __align__(128) char smem[];
    const int which = blockIdx.x >> 3;
    const int n0 = (blockIdx.x & 7) * 128;
    const int m0 = blockIdx.y * 128;
    __half* outH = which == 0 ? g_qh : which == 1 ? g_kh : g_vh;
    __half* outL = which == 0 ? g_ql : which == 1 ? g_kl : g_vl;
    gemm_core<1>(g_xh, g_xl, g_wh[which], nullptr, outH, outL, smem, m0, n0);
}

__global__ __launch_bounds__(256) void wo_gemm(float* __restrict__ out) {
    extern __shared__ __align__(128) char smem[];
    gemm_core<0>(g_ah, g_al, g_wh[3], out, nullptr, nullptr,
                 smem, blockIdx.y * 128, blockIdx.x * 128);
}

// ---------------------------------------------------------------------------
// Flash attention: S = Qh*Kh (f32-acc) + [Qh*Kl + Ql*Kh] (f16-acc, folded);
// PV = Ph*Vh (f32-acc) + Ph*Vl (f16-acc, folded). Causal, double-buffered K/V.
// ---------------------------------------------------------------------------
#define KSB 144
#define OQH 0
#define OQL (OQH + 128 * KSB)
#define OKV (OQL + 128 * KSB)            // 36864
#define KVSTG (4 * 64 * KSB)             // 36864
#define FLASH_SMEM (OKV + 2 * KVSTG)     // 110592

__global__ __launch_bounds__(256, 2) void flash_hmma() {
    extern __shared__ __align__(128) char smem[];
    const uint32_t sb = smem_u32(smem);

    const int tid = threadIdx.x;
    const int w = tid >> 5;
    const int lane = tid & 31;
    const int g = lane >> 2, tig = lane & 3;
    const int q0 = ((int)gridDim.x - 1 - (int)blockIdx.x) * 128;
    const int bh = blockIdx.y;
    const int b = bh / HH, h = bh % HH;
    const int row0 = q0 + w * 16;

    const __half* Qh_g = g_qh + (size_t)bh * TT * DD;
    const __half* Ql_g = g_ql + (size_t)bh * TT * DD;
    const __half* Kh_g = g_kh + (size_t)bh * TT * DD;
    const __half* Kl_g = g_kl + (size_t)bh * TT * DD;
    const __half* Vh_g = g_vh + (size_t)bh * TT * DD;
    const __half* Vl_g = g_vl + (size_t)bh * TT * DD;

#pragma unroll
    for (int it = 0; it < 8; it++) {
        const int idx = it * 256 + tid;
        const int mat = idx >> 10;
        const int r = (idx >> 3) & 127, c = idx & 7;
        const __half* src = (mat ? Ql_g : Qh_g) + (size_t)(q0 + r) * DD + c * 8;
        cp16(sb + (mat ? OQL : OQH) + r * KSB + c * 16, src);
    }
    cp_commit();

    auto kv_load = [&](int kt, int st) {
        const int k0 = kt << 6;
        const uint32_t base = sb + OKV + st * KVSTG;
#pragma unroll
        for (int it = 0; it < 8; it++) {
            const int idx = it * 256 + tid;
            const int mat = idx >> 9;     // 0:Kh 1:Kl 2:Vh 3:Vl
            const int r = (idx >> 3) & 63, c = idx & 7;
            const __half* src =
                (mat == 0 ? Kh_g : mat == 1 ? Kl_g : mat == 2 ? Vh_g : Vl_g)
                + (size_t)(k0 + r) * DD + c * 8;
            cp16(base + mat * (64 * KSB) + r * KSB + c * 16, src);
        }
        cp_commit();
    };

    float o[8][4] = {};
    float mrow[2] = {-1e30f, -1e30f}, lrow[2] = {0.f, 0.f};
    const int nkt = (q0 >> 6) + 2;

    kv_load(0, 0);

    for (int kt = 0; kt < nkt; kt++) {
        const int k0 = kt << 6;
        const int st = kt & 1;
        if (kt + 1 < nkt) { kv_load(kt + 1, st ^ 1); cp_wait<1>(); }
        else              { cp_wait<0>(); }
        __syncthreads();

        const uint32_t kvb = sb + OKV + st * KVSTG;
        const uint32_t sKH = kvb, sKL = kvb + 64 * KSB;
        const uint32_t sVH = kvb + 2 * 64 * KSB, sVL = kvb + 3 * 64 * KSB;

        if (k0 <= row0 + 15) {
            // ---- S = Q K^T : main f32-acc, corrections f16-acc ----
            float s[8][4] = {};
#pragma unroll
            for (int ks = 0; ks < 4; ks++) {
                uint32_t qh[4], ql[4];
                const uint32_t ao = (w * 16 + (lane & 15)) * KSB + (lane >> 4) * 16 + ks * 32;
                ldsm4(qh, sb + OQH + ao);
                ldsm4(ql, sb + OQL + ao);
#pragma unroll
                for (int n16 = 0; n16 < 4; n16++) {
                    uint32_t kh[4], kl[4];
                    const uint32_t bo = (n16 * 16 + (lane & 7) + ((lane >> 4) & 1) * 8) * KSB
                                        + ((lane >> 3) & 1) * 16 + ks * 32;
                    ldsm4(kh, sKH + bo);
                    ldsm4(kl, sKL + bo);
#pragma unroll
                    for (int h2 = 0; h2 < 2; h2++) {
                        const int nt = n16 * 2 + h2;
                        mma16816(s[nt], qh, &kh[h2 * 2]);
                        uint32_t c0 = 0, c1 = 0;
                        mma16816h(c0, c1, qh, &kl[h2 * 2]);
                        mma16816h(c0, c1, ql, &kh[h2 * 2]);
                        fold_h2(s[nt], c0, c1);
                    }
                }
            }

            // ---- causal mask ----
            if (k0 + 63 > row0) {
#pragma unroll
                for (int nt = 0; nt < 8; nt++)
#pragma unroll
                    for (int e = 0; e < 4; e++) {
                        const int col = k0 + nt * 8 + tig * 2 + (e & 1);
                        const int row = row0 + g + (e >> 1) * 8;
                        if (col > row) s[nt][e] = -1e30f;
                    }
            }

            // ---- online softmax on fragments ----
            const unsigned FULL = 0xffffffffu;
#pragma unroll
            for (int p2 = 0; p2 < 2; p2++) {
                float mx = -1e30f;
#pragma unroll
                for (int nt = 0; nt < 8; nt++)
                    mx = fmaxf(mx, fmaxf(s[nt][p2 * 2], s[nt][p2 * 2 + 1]));
                mx *= 0.125f;
                mx = fmaxf(mx, __shfl_xor_sync(FULL, mx, 1));
                mx = fmaxf(mx, __shfl_xor_sync(FULL, mx, 2));
                const float m_new = fmaxf(mrow[p2], mx);
                const float corr = __expf(mrow[p2] - m_new);
                float sum = 0.f;
#pragma unroll
                for (int nt = 0; nt < 8; nt++) {
                    const float e0 = __expf(s[nt][p2 * 2]     * 0.125f - m_new);
                    const float e1 = __expf(s[nt][p2 * 2 + 1] * 0.125f - m_new);
                    s[nt][p2 * 2] = e0; s[nt][p2 * 2 + 1] = e1;
                    sum += e0 + e1;
                }
                sum += __shfl_xor_sync(FULL, sum, 1);
                sum += __shfl_xor_sync(FULL, sum, 2);
                lrow[p2] = lrow[p2] * corr + sum;
                mrow[p2] = m_new;
#pragma unroll
                for (int nt = 0; nt < 8; nt++) {
                    o[nt][p2 * 2] *= corr; o[nt][p2 * 2 + 1] *= corr;
                }
            }

            // ---- O += P V : Ph*Vh f32-acc, Ph*Vl f16-acc folded ----
#pragma unroll
            for (int ks = 0; ks < 4; ks++) {
                uint32_t aH[4];
                aH[0] = pack_h2(s[2 * ks][0],     s[2 * ks][1]);
                aH[1] = pack_h2(s[2 * ks][2],     s[2 * ks][3]);
                aH[2] = pack_h2(s[2 * ks + 1][0], s[2 * ks + 1][1]);
                aH[3] = pack_h2(s[2 * ks + 1][2], s[2 * ks + 1][3]);
#pragma unroll
                for (int n16 = 0; n16 < 4; n16++) {
                    uint32_t vh[4], vl[4];
                    const uint32_t vo = (ks * 16 + (lane & 15)) * KSB
                                        + n16 * 32 + ((lane >> 4) & 1) * 16;
                    ldsm4t(vh, sVH + vo);
                    ldsm4t(vl, sVL + vo);
#pragma unroll
                    for (int h2 = 0; h2 < 2; h2++) {
                        const int nt = n16 * 2 + h2;
                        mma16816(o[nt], aH, &vh[h2 * 2]);
                        uint32_t c0 = 0, c1 = 0;
                        mma16816h(c0, c1, aH, &vl[h2 * 2]);
                        fold_h2(o[nt], c0, c1);
                    }
                }
            }
        }
        __syncthreads();
    }

    // ---- normalize + fp16 hi/lo split into Wo GEMM inputs ----
#pragma unroll
    for (int p2 = 0; p2 < 2; p2++) {
        const float inv = 1.0f / lrow[p2];
        const int r = row0 + g + p2 * 8;
        const size_t base = ((size_t)(b * TT + r)) * CC + h * DD;
#pragma unroll
        for (int nt = 0; nt < 8; nt++) {
            uint32_t ph, pl;
            splitpack(o[nt][p2 * 2] * inv, o[nt][p2 * 2 + 1] * inv, ph, pl);
            *(uint32_t*)(g_ah + base + nt * 8 + tig * 2) = ph;
            *(uint32_t*)(g_al + base + nt * 8 + tig * 2) = pl;
        }
    }
}

// ---------------------------------------------------------------------------
extern "C" void kernel_launch(void* const* d_in, const int* in_sizes, int n_in,
                              void* d_out, int out_size) {
    const float* x  = (const float*)d_in[0];
    const float* Wq = (const float*)d_in[1];
    const float* Wk = (const float*)d_in[2];
    const float* Wv = (const float*)d_in[3];
    const float* Wo = (const float*)d_in[4];
    float* out = (float*)d_out;

    __half *xh, *xl, *wh;
    cudaGetSymbolAddress((void**)&xh, g_xh);
    cudaGetSymbolAddress((void**)&xl, g_xl);
    cudaGetSymbolAddress((void**)&wh, g_wh);

    split_half<<<(MM * CC / 4 + 255) / 256, 256>>>(x, xh, xl, MM * CC / 4);
    split_w4<<<dim3((CC * CC / 4 + 255) / 256, 4), 256>>>(Wq, Wk, Wv, Wo, wh);

    const int gemm_smem = 2 * STAGEB;  // 61440
    cudaFuncSetAttribute(qkv_gemm, cudaFuncAttributeMaxDynamicSharedMemorySize, gemm_smem);
    cudaFuncSetAttribute(wo_gemm, cudaFuncAttributeMaxDynamicSharedMemorySize, gemm_smem);
    cudaFuncSetAttribute(flash_hmma, cudaFuncAttributeMaxDynamicSharedMemorySize, FLASH_SMEM);

    qkv_gemm<<<dim3(24, MM / 128), 256, gemm_smem>>>();

    flash_hmma<<<dim3(TT / 128, BB * HH), 256, FLASH_SMEM>>>();

    wo_gemm<<<dim3(CC / 128, MM / 128), 256, gemm_smem>>>(out);
}